// round 11
// baseline (speedup 1.0000x reference)
#include <cuda_runtime.h>
#include <cstdint>

#define H 1024
#define BZd 256
#define NKEYS 131072
#define NU 7

#define SK 21.0f
#define SR 750.0f
#define DQI (1.0f / 750.0f)   // s32 accum -> int8 Krot (scale 21): acc/(21*750)*21

__constant__ int c_ud[NU]   = {256, 256, 128, 128, 128, 64, 64};
__constant__ int c_uoff[NU] = {0, 256, 512, 640, 768, 896, 960};

__device__ int8_t g_keys8[(size_t)NKEYS * H];  // keys quantized (x21)
__device__ int8_t g_Rt8[H * H];                // R^T quantized (x750), [n][k] k fast
__device__ int8_t g_q8[BZd * H];               // qrot quantized per-(b,u) rowmax
__device__ float g_qrot[BZd * H];
__device__ unsigned long long g_best[NU * BZd];
__device__ float g_cos[NU * BZd];

// ---------------- smem layout (32-bit word offsets) ----------------
#define OF_K8 0                          // Krot8 panel [128 keys][272 B] = 8704 w
#define OF_STA(b) (8704 + (b) * 2560)    // GEMM1 A stages x3: [128 rows][80 B]
#define OF_STB(b) (16384 + (b) * 2560)   // GEMM1 B stages x3
#define OF_STQ(b) (8704 + (b) * 5120)    // GEMM2 Q stages x3: [256 rows][80 B] (alias)
#define OF_PART 24064                    // 256 floats
#define OF_RN 24320                      // 128 floats
#define OF_WMAX 24448                    // 512 u64 = 1024 words
#define SMEM_WORDS 25472
#define SMEM_BYTES (SMEM_WORDS * 4)      // 101888

// ---------------- PTX helpers ----------------
#define CPA16(dst, src) \
    asm volatile("cp.async.cg.shared.global [%0], [%1], 16;" :: "r"(dst), "l"(src))
#define CPCOMMIT asm volatile("cp.async.commit_group;" ::: "memory")
#define CPWAIT1 asm volatile("cp.async.wait_group 1;" ::: "memory")
#define CPWAIT0 asm volatile("cp.async.wait_group 0;" ::: "memory")

__device__ __forceinline__ void mma_s8(int* d, const uint32_t* a, const uint32_t* b) {
    asm volatile(
        "mma.sync.aligned.m16n8k32.row.col.s32.s8.s8.s32 "
        "{%0,%1,%2,%3},{%4,%5,%6,%7},{%8,%9},{%0,%1,%2,%3};"
        : "+r"(d[0]), "+r"(d[1]), "+r"(d[2]), "+r"(d[3])
        : "r"(a[0]), "r"(a[1]), "r"(a[2]), "r"(a[3]), "r"(b[0]), "r"(b[1]));
}

__device__ __forceinline__ void ldsm4(uint32_t* r, uint32_t addr) {
    asm volatile("ldmatrix.sync.aligned.m8n8.x4.shared.b16 {%0,%1,%2,%3}, [%4];"
                 : "=r"(r[0]), "=r"(r[1]), "=r"(r[2]), "=r"(r[3]) : "r"(addr));
}

__device__ __forceinline__ unsigned long long umax64(unsigned long long a,
                                                     unsigned long long b) {
    return a > b ? a : b;
}

__device__ __forceinline__ int8_t q8clamp(float v) {
    int x = __float2int_rn(v);
    x = x > 127 ? 127 : (x < -127 ? -127 : x);
    return (int8_t)x;
}

// ================= quantization =================
__global__ void quant_keys(const float* __restrict__ keys) {
    size_t i = (size_t)blockIdx.x * blockDim.x + threadIdx.x;  // float4 index
    float4 v = ((const float4*)keys)[i];
    char4 c;
    c.x = q8clamp(v.x * SK); c.y = q8clamp(v.y * SK);
    c.z = q8clamp(v.z * SK); c.w = q8clamp(v.w * SK);
    ((char4*)g_keys8)[i] = c;
}

__global__ void quant_Rt(const float* __restrict__ R) {
    __shared__ float tl[32][33];
    const int bx = blockIdx.x * 32, by = blockIdx.y * 32;
    const int tx = threadIdx.x, ty = threadIdx.y;
#pragma unroll
    for (int i = 0; i < 32; i += 8)
        tl[ty + i][tx] = R[(size_t)(by + ty + i) * H + bx + tx];
    __syncthreads();
#pragma unroll
    for (int i = 0; i < 32; i += 8)
        g_Rt8[(size_t)(bx + ty + i) * H + by + tx] = q8clamp(tl[tx][ty + i] * SR);
}

// ================= K1a: qrot = query @ R (exact fp32) =================
__global__ void qrot_kernel(const float* __restrict__ q, const float* __restrict__ R) {
    __shared__ float sq[2 * H];
    const int b0 = blockIdx.x * 2;
    const int t = threadIdx.x;
    for (int i = t; i < 2 * H; i += 256) sq[i] = q[(size_t)b0 * H + i];
    __syncthreads();
    float acc[2][4] = {};
    for (int i = 0; i < H; ++i) {
        const float* Rr = R + (size_t)i * H;
        float r0 = Rr[t], r1 = Rr[t + 256], r2 = Rr[t + 512], r3 = Rr[t + 768];
        float q0 = sq[i], q1 = sq[H + i];
        acc[0][0] += q0 * r0; acc[0][1] += q0 * r1;
        acc[0][2] += q0 * r2; acc[0][3] += q0 * r3;
        acc[1][0] += q1 * r0; acc[1][1] += q1 * r1;
        acc[1][2] += q1 * r2; acc[1][3] += q1 * r3;
    }
#pragma unroll
    for (int bb = 0; bb < 2; ++bb)
#pragma unroll
        for (int jj = 0; jj < 4; ++jj)
            g_qrot[(size_t)(b0 + bb) * H + t + jj * 256] = acc[bb][jj];
}

// ================= K1b: per-(b,u) rowmax quantize qrot -> g_q8; init g_best =====
// (per-(b,u) positive scale cancels in argmax over keys)
__global__ void qhat_kernel() {
    __shared__ float sx[H];
    __shared__ float sred[256];
    const int b = blockIdx.x, t = threadIdx.x;
    for (int i = t; i < H; i += 256) sx[i] = g_qrot[(size_t)b * H + i];
    if (b == 0) {
        for (int k = t; k < NU * BZd; k += 256) g_best[k] = 0x3FFFFFFF00000000ULL;
    }
    __syncthreads();
    for (int u = 0; u < NU; ++u) {
        const int d = c_ud[u], off = c_uoff[u];
        float m = 0.0f;
        for (int c = t; c < d; c += 256) m = fmaxf(m, fabsf(sx[off + c]));
        sred[t] = m;
        __syncthreads();
        for (int w = 128; w > 0; w >>= 1) {
            if (t < w) sred[t] = fmaxf(sred[t], sred[t + w]);
            __syncthreads();
        }
        float scale = 127.0f / fmaxf(sred[0], 1e-20f);
        __syncthreads();
        for (int c = t; c < d; c += 256)
            g_q8[(size_t)b * H + off + c] = q8clamp(sx[off + c] * scale);
    }
}

// ================= K2: scan (all-int8 mma, ldmatrix) =================
// grid 1024 x 128 keys, block 256 (8 warps)
struct ScanCtx {
    float* sm;
    uint32_t* smw;
    uint32_t sb4;
    int t, lane, w, L0;
    int m0g1, n0g1, m0g2, n0g2;
    uint32_t offA1, offB1, offA2, offB2;
};

// stage int8: 128 rows x 64 bytes (k-chunk of 64), row pitch 80 B
__device__ __forceinline__ void stage_g1(const ScanCtx& cx, int p, int kk, int buf) {
    const int row = cx.t >> 1, hf = cx.t & 1;
    {
        const int8_t* src = g_keys8 + (size_t)(cx.L0 + row) * H + kk * 64 + hf * 32;
        const uint32_t dst = cx.sb4 + OF_STA(buf) * 4 + row * 80 + hf * 32;
        CPA16(dst, src);
        CPA16(dst + 16, src + 16);
    }
    {
        const int8_t* src = g_Rt8 + (size_t)(p * 128 + row) * H + kk * 64 + hf * 32;
        const uint32_t dst = cx.sb4 + OF_STB(buf) * 4 + row * 80 + hf * 32;
        CPA16(dst, src);
        CPA16(dst + 16, src + 16);
    }
}

// stage Q int8: 256 rows x 64 bytes, pitch 80 B
__device__ __forceinline__ void stage_q(const ScanCtx& cx, int qoffB, int buf) {
    const int8_t* src = g_q8 + (size_t)cx.t * H + qoffB;
    const uint32_t dst = cx.sb4 + OF_STQ(buf) * 4 + cx.t * 80;
    CPA16(dst, src);
    CPA16(dst + 16, src + 16);
    CPA16(dst + 32, src + 32);
    CPA16(dst + 48, src + 48);
}

// GEMM1 (int8): Krot8 panel cols [kdstB, kdstB+128) = keys[128,1024] @ R[:, p*128:+128]
__device__ __forceinline__ void g1_panel(const ScanCtx& cx, int p, int kdstB) {
    int acc1[2][8][4] = {};
    stage_g1(cx, p, 0, 0); CPCOMMIT;
    stage_g1(cx, p, 1, 1); CPCOMMIT;
    for (int kk = 0; kk < 16; ++kk) {
        if (kk < 15) { CPWAIT1; } else { CPWAIT0; }
        __syncthreads();
        if (kk + 2 < 16) { stage_g1(cx, p, kk + 2, (kk + 2) % 3); CPCOMMIT; }
        const uint32_t baseA = cx.sb4 + OF_STA(kk % 3) * 4 + cx.offA1;
        const uint32_t baseB = cx.sb4 + OF_STB(kk % 3) * 4 + cx.offB1;
#pragma unroll
        for (int k32 = 0; k32 < 2; ++k32) {
            uint32_t a[2][4];
            ldsm4(a[0], baseA + k32 * 32);
            ldsm4(a[1], baseA + 1280 + k32 * 32);
            uint32_t bb[4][4];
#pragma unroll
            for (int jj = 0; jj < 4; ++jj)
                ldsm4(bb[jj], baseB + jj * 1280 + k32 * 32);
#pragma unroll
            for (int jj = 0; jj < 4; ++jj) {
                mma_s8(acc1[0][2 * jj],     a[0], &bb[jj][0]);
                mma_s8(acc1[0][2 * jj + 1], a[0], &bb[jj][2]);
                mma_s8(acc1[1][2 * jj],     a[1], &bb[jj][0]);
                mma_s8(acc1[1][2 * jj + 1], a[1], &bb[jj][2]);
            }
        }
    }
    // dequantize s32 accum -> int8 Krot panel (scale 21)
    char* Kc = (char*)cx.sm;
#pragma unroll
    for (int i = 0; i < 2; ++i)
#pragma unroll
        for (int j = 0; j < 8; ++j) {
            const int row = cx.m0g1 + 16 * i + (cx.lane >> 2);
            const int col = kdstB + cx.n0g1 + 8 * j + (cx.lane & 3) * 2;
            int c0 = (int)q8clamp((float)acc1[i][j][0] * DQI);
            int c1 = (int)q8clamp((float)acc1[i][j][1] * DQI);
            int c2 = (int)q8clamp((float)acc1[i][j][2] * DQI);
            int c3 = (int)q8clamp((float)acc1[i][j][3] * DQI);
            *(short*)(Kc + row * 272 + col) = (short)((c0 & 0xFF) | (c1 << 8));
            *(short*)(Kc + (row + 8) * 272 + col) = (short)((c2 & 0xFF) | (c3 << 8));
        }
    __syncthreads();
}

// per-key inverse norms over W cols starting at byte cb (dp4a on int8 panel)
__device__ __forceinline__ void norms(const ScanCtx& cx, int W, int cb) {
    const int key = cx.t & 127, h = cx.t >> 7;
    const int cnt = W >> 3;  // uints per half
    const uint32_t* base =
        (const uint32_t*)((const char*)cx.sm + key * 272 + cb + h * (W >> 1));
    int s = 0;
#pragma unroll 16
    for (int i = 0; i < cnt; ++i) s = __dp4a((int)base[i], (int)base[i], s);
    cx.sm[OF_PART + cx.t] = (float)s;
    __syncthreads();
    if (cx.t < 128) {
        float tot = cx.sm[OF_PART + cx.t] + cx.sm[OF_PART + cx.t + 128];
        float norm = sqrtf(tot) * (1.0f / 21.0f);
        cx.sm[OF_RN + cx.t] = 1.0f / fmaxf(norm, 1e-3f);
    }
    __syncthreads();
}

// GEMM2 (int8): sims[256 q x 128 keys] over unit cols; argmax resolve
__device__ __forceinline__ void g2_resolve(const ScanCtx& cx, int u, int d,
                                           int qoffB, int cbB) {
    int acc2[4][8][4] = {};
    const int nch = d >> 6;  // chunks of 64 bytes (>=1)
    stage_q(cx, qoffB, 0); CPCOMMIT;
    if (nch > 1) { stage_q(cx, qoffB + 64, 1); CPCOMMIT; }
    for (int kc = 0; kc < nch; ++kc) {
        if (kc < nch - 1) { CPWAIT1; } else { CPWAIT0; }
        __syncthreads();
        if (kc + 2 < nch) { stage_q(cx, qoffB + (kc + 2) * 64, (kc + 2) % 3); CPCOMMIT; }
        const uint32_t baseQ = cx.sb4 + OF_STQ(kc % 3) * 4 + cx.offA2;
#pragma unroll
        for (int k32 = 0; k32 < 2; ++k32) {
            const int kwB = kc * 64 + k32 * 32;
            const uint32_t baseK = cx.sb4 + cbB + kwB + cx.offB2;  // OF_K8 = 0
            uint32_t a[4][4];
#pragma unroll
            for (int i = 0; i < 4; ++i)
                ldsm4(a[i], baseQ + i * 1280 + k32 * 32);
            uint32_t bb[4][4];
#pragma unroll
            for (int jj = 0; jj < 4; ++jj)
                ldsm4(bb[jj], baseK + jj * 4352);  // 16 keys * 272B
#pragma unroll
            for (int jj = 0; jj < 4; ++jj)
#pragma unroll
                for (int i = 0; i < 4; ++i) {
                    mma_s8(acc2[i][2 * jj],     a[i], &bb[jj][0]);
                    mma_s8(acc2[i][2 * jj + 1], a[i], &bb[jj][2]);
                }
        }
    }
    // resolve (per-key scale rk; per-b scale cancels in argmax)
    float rk[8][2];
#pragma unroll
    for (int j = 0; j < 8; ++j) {
        const int kl = cx.n0g2 + 8 * j + (cx.lane & 3) * 2;
        rk[j][0] = cx.sm[OF_RN + kl];
        rk[j][1] = cx.sm[OF_RN + kl + 1];
    }
    unsigned long long* wmax = (unsigned long long*)(cx.sm + OF_WMAX);
#pragma unroll
    for (int i = 0; i < 4; ++i)
#pragma unroll
        for (int hh = 0; hh < 2; ++hh) {
            const int q = cx.m0g2 + 16 * i + (cx.lane >> 2) + 8 * hh;
            unsigned long long best = 0ULL;
#pragma unroll
            for (int j = 0; j < 8; ++j)
#pragma unroll
                for (int e = 0; e < 2; ++e) {
                    float v = (float)acc2[i][j][hh * 2 + e] * rk[j][e];
                    unsigned uv = __float_as_uint(v);
                    uv = (uv & 0x80000000u) ? ~uv : (uv | 0x80000000u);
                    const int kg = cx.L0 + cx.n0g2 + 8 * j + (cx.lane & 3) * 2 + e;
                    unsigned long long pk = ((unsigned long long)uv << 32) |
                                            (unsigned long long)(0xFFFFFFFFu - (unsigned)kg);
                    best = umax64(best, pk);
                }
            best = umax64(best, __shfl_xor_sync(0xFFFFFFFFu, best, 1));
            best = umax64(best, __shfl_xor_sync(0xFFFFFFFFu, best, 2));
            if ((cx.lane & 3) == 0) wmax[q * 2 + (cx.w & 1)] = best;
        }
    __syncthreads();
    {
        unsigned long long m = umax64(wmax[cx.t * 2], wmax[cx.t * 2 + 1]);
        atomicMax(&g_best[u * BZd + cx.t], m);
    }
    __syncthreads();
}

__global__ void __launch_bounds__(256, 1) scan_kernel() {
    extern __shared__ float sm[];
    ScanCtx cx;
    cx.sm = sm;
    cx.smw = (uint32_t*)sm;
    cx.sb4 = (uint32_t)__cvta_generic_to_shared(sm);
    cx.t = threadIdx.x;
    cx.lane = cx.t & 31;
    cx.w = cx.t >> 5;
    cx.L0 = blockIdx.x * 128;
    cx.m0g1 = (cx.w >> 1) * 32;
    cx.n0g1 = (cx.w & 1) * 64;
    cx.m0g2 = (cx.w >> 1) * 64;
    cx.n0g2 = (cx.w & 1) * 64;
    {
        const int l = cx.lane;
        cx.offA1 = (uint32_t)((cx.m0g1 + (l & 7) + 8 * ((l >> 3) & 1)) * 80 + 16 * (l >> 4));
        cx.offA2 = (uint32_t)((cx.m0g2 + (l & 7) + 8 * ((l >> 3) & 1)) * 80 + 16 * (l >> 4));
        cx.offB1 = (uint32_t)((cx.n0g1 + (l & 7) + 8 * (l >> 4)) * 80 + 16 * ((l >> 3) & 1));
        cx.offB2 = (uint32_t)((cx.n0g2 + (l & 7) + 8 * (l >> 4)) * 272 + 16 * ((l >> 3) & 1));
    }

    // unit 0: cols 0..255
    g1_panel(cx, 0, 0);
    g1_panel(cx, 1, 128);
    norms(cx, 256, 0);
    g2_resolve(cx, 0, 256, 0, 0);
    // unit 1: cols 256..511
    g1_panel(cx, 2, 0);
    g1_panel(cx, 3, 128);
    norms(cx, 256, 0);
    g2_resolve(cx, 1, 256, 256, 0);
    // units 2..4: 128 cols each
    g1_panel(cx, 4, 0);
    norms(cx, 128, 0);
    g2_resolve(cx, 2, 128, 512, 0);
    g1_panel(cx, 5, 0);
    norms(cx, 128, 0);
    g2_resolve(cx, 3, 128, 640, 0);
    g1_panel(cx, 6, 0);
    norms(cx, 128, 0);
    g2_resolve(cx, 4, 128, 768, 0);
    // units 5,6: 64 cols each, share panel 7
    g1_panel(cx, 7, 0);
    norms(cx, 64, 0);
    g2_resolve(cx, 5, 64, 896, 0);
    norms(cx, 64, 64);
    g2_resolve(cx, 6, 64, 960, 64);
}

// ================= K3: exact fp32 cosine, 4 queries per block =================
// grid 7*64: u = blk/64, b0 = (blk%64)*4
__global__ void final_kernel(const float* __restrict__ keys, const float* __restrict__ R) {
    __shared__ float sv[4][H];
    __shared__ float sred[256];
    const int u = blockIdx.x >> 6;
    const int b0 = (blockIdx.x & 63) * 4;
    const int t = threadIdx.x;
#pragma unroll
    for (int g = 0; g < 4; ++g) {
        unsigned long long pk = g_best[u * BZd + b0 + g];
        unsigned idx = 0xFFFFFFFFu - (unsigned)(pk & 0xFFFFFFFFull);
        const float* v = keys + (size_t)idx * H;
        for (int i = t; i < H; i += 256) sv[g][i] = v[i];
    }
    __syncthreads();
    const int d = c_ud[u], off = c_uoff[u];
    const int rep = 256 / d;
    const int ip = t / d;
    const int c = t - ip * d;
    const int chunk = H / rep;
    const int i0 = ip * chunk;
    float dg[4] = {};
    {
        const float* Rc = R + off + c;
#pragma unroll 2
        for (int i = i0; i < i0 + chunk; ++i) {
            float r = Rc[(size_t)i * H];
            dg[0] += sv[0][i] * r;
            dg[1] += sv[1][i] * r;
            dg[2] += sv[2][i] * r;
            dg[3] += sv[3][i] * r;
        }
    }
#pragma unroll
    for (int g = 0; g < 4; ++g) {
        sred[t] = dg[g];
        __syncthreads();
        float dgf = 0.0f, qc = 0.0f;
        if (t < d) {
            dgf = sred[t];
            for (int r = 1; r < rep; ++r) dgf += sred[t + r * d];
            qc = g_qrot[(size_t)(b0 + g) * H + off + t];
        }
        __syncthreads();
        float vals[3] = {qc * dgf, dgf * dgf, qc * qc};
        float tot[3];
#pragma unroll
        for (int r = 0; r < 3; ++r) {
            sred[t] = vals[r];
            __syncthreads();
            for (int w = 128; w > 0; w >>= 1) {
                if (t < w) sred[t] += sred[t + w];
                __syncthreads();
            }
            tot[r] = sred[0];
            __syncthreads();
        }
        if (t == 0) {
            float cosv = tot[0] / (fmaxf(sqrtf(tot[2]), 1e-8f) * fmaxf(sqrtf(tot[1]), 1e-8f));
            g_cos[u * BZd + b0 + g] = cosv * (float)d;
        }
    }
}

// ================= K4: deterministic reduction =================
__global__ void reduce_kernel(float* __restrict__ out) {
    __shared__ float sred[256];
    const int t = threadIdx.x;
    float s = 0.0f;
    for (int k = t; k < NU * BZd; k += 256) s += g_cos[k];
    sred[t] = s;
    __syncthreads();
    for (int w = 128; w > 0; w >>= 1) {
        if (t < w) sred[t] += sred[t + w];
        __syncthreads();
    }
    if (t == 0) out[0] = -sred[0] / (float)(BZd * H);
}

// ================= launch =================
extern "C" void kernel_launch(void* const* d_in, const int* in_sizes, int n_in,
                              void* d_out, int out_size) {
    const float* query = nullptr;
    const float* keys = nullptr;
    const float* R = nullptr;
    for (int i = 0; i < n_in; ++i) {
        if (in_sizes[i] == BZd * H) query = (const float*)d_in[i];
        else if (in_sizes[i] == NKEYS * H) keys = (const float*)d_in[i];
        else if (in_sizes[i] == H * H) R = (const float*)d_in[i];
    }
    if (!query) query = (const float*)d_in[0];
    if (!keys) keys = (const float*)d_in[1];
    if (!R) R = (const float*)d_in[2];
    float* out = (float*)d_out;

    cudaFuncSetAttribute(scan_kernel, cudaFuncAttributeMaxDynamicSharedMemorySize, SMEM_BYTES);

    quant_keys<<<(int)((size_t)NKEYS * H / 4 / 256), 256>>>(keys);
    quant_Rt<<<dim3(32, 32), dim3(32, 8)>>>(R);
    qrot_kernel<<<128, 256>>>(query, R);
    qhat_kernel<<<256, 256>>>();
    scan_kernel<<<1024, 256, SMEM_BYTES>>>();
    final_kernel<<<NU * 64, 256>>>(keys, R);
    reduce_kernel<<<1, 256>>>(out);
}